// round 4
// baseline (speedup 1.0000x reference)
#include <cuda_runtime.h>
#include <math.h>
#include <stdint.h>

// ============================================================================
// TemporalSamplingUpSampler — 3-phase:
//   1) plan_kernel  <<<1,32>>>  : shfl-only warp plan (softmax -> Lp,
//                                 r = rint, prefix sum, total, l_max).
//   2) expand_kernel<<<128,256>>>: plan -> smem, per-column (k, w) via
//                                 LDS binary search. Writes d_w[T], d_k[T].
//   3) fill_kernel  (hot)       : out[c,tt] = A[c,k[tt]] * w[tt].
//                                 Batched A prefetch (MLP=8) + float4
//                                 evict-first stores. HBM-write bound.
// ============================================================================

#define MAX_K 1024
#define MAX_T (1 << 18)
#define CPB   8            // c-rows per fill block (compile-time)

__device__ float d_Lp[MAX_K];
__device__ int   d_cum[MAX_K + 1];
__device__ int   d_total;
__device__ float d_lmaxf;

__device__ float d_w[MAX_T];
__device__ int   d_k[MAX_T];

// ---------------------------------------------------------------------------
// Plan kernel: ONE warp, shfl-only, no barriers.
// ---------------------------------------------------------------------------
__global__ void __launch_bounds__(32) plan_kernel(
    const float* __restrict__ L, int K, float Tf)
{
    const int lane = threadIdx.x;
    const int KPL  = (K + 31) >> 5;
    const int base = lane * KPL;

    // cache this lane's L values in registers (KPL <= 32)
    float lv[32];
#pragma unroll 8
    for (int i = 0; i < KPL; i++) {
        int k = base + i;
        lv[i] = (k < K) ? __ldg(L + k) : -INFINITY;
    }

    // max(L)
    float mx = -INFINITY;
    for (int i = 0; i < KPL; i++) mx = fmaxf(mx, lv[i]);
    for (int o = 16; o; o >>= 1) mx = fmaxf(mx, __shfl_xor_sync(0xffffffffu, mx, o));

    // sum(exp)
    float e[32];
    float sum = 0.0f;
    for (int i = 0; i < KPL; i++) {
        int k = base + i;
        e[i] = (k < K) ? expf(lv[i] - mx) : 0.0f;
        sum += e[i];
    }
    for (int o = 16; o; o >>= 1) sum += __shfl_xor_sync(0xffffffffu, sum, o);

    // Lp, max(Lp), per-lane length total
    float maxLp = -INFINITY;
    int lane_total = 0;
    int rr[32];
    for (int i = 0; i < KPL; i++) {
        int k = base + i;
        if (k < K) {
            float Lp = Tf * __fdiv_rn(e[i], sum);
            d_Lp[k] = Lp;
            maxLp = fmaxf(maxLp, Lp);
            int r = (int)rintf(Lp);        // half-to-even == np.rint
            if (r < 0) r = 0;
            rr[i] = r;
            lane_total += r;
        } else rr[i] = 0;
    }
    for (int o = 16; o; o >>= 1) maxLp = fmaxf(maxLp, __shfl_xor_sync(0xffffffffu, maxLp, o));

    // inclusive scan of lane totals
    int incl = lane_total;
    for (int o = 1; o < 32; o <<= 1) {
        int v = __shfl_up_sync(0xffffffffu, incl, o);
        if (lane >= o) incl += v;
    }
    int running = incl - lane_total;       // exclusive
    const int total = __shfl_sync(0xffffffffu, incl, 31);

    for (int i = 0; i < KPL; i++) {
        int k = base + i;
        if (k < K) {
            running += rr[i];
            d_cum[k + 1] = running;
        }
    }
    if (lane == 0) {
        d_cum[0] = 0;
        d_total  = total;
        double dm = (double)maxLp + 0.5;
        d_lmaxf = (float)(long long)dm;    // int(max+0.5), trunc==floor (>=0)
    }
}

// ---------------------------------------------------------------------------
// Expand kernel: plan -> smem, then 4 columns/thread.
// ---------------------------------------------------------------------------
__global__ void __launch_bounds__(256) expand_kernel(int K, int T)
{
    __shared__ float s_Lp[MAX_K];
    __shared__ int   s_cum[MAX_K + 1];

    for (int k = threadIdx.x; k < K; k += blockDim.x) {
        s_Lp[k]      = d_Lp[k];
        s_cum[k + 1] = d_cum[k + 1];
    }
    if (threadIdx.x == 0) s_cum[0] = 0;
    __syncthreads();

    const int tt0 = (blockIdx.x * blockDim.x + threadIdx.x) * 4;
    if (tt0 >= T) return;

    const int   total = d_total;
    const float lmaxf = d_lmaxf;

    const bool  pow2  = (T & (T - 1)) == 0;
    const int   shift = __ffs(T) - 1;
    const double ratio = (double)total / (double)T;

    float wv[4];
    int   kv[4];

#pragma unroll
    for (int i = 0; i < 4; i++) {
        int tt = tt0 + i;
        if (tt > T - 1) tt = T - 1;

        long long slot;
        if (pow2) {
            slot = ((long long)tt * (long long)total) >> shift;  // exact
        } else {
            slot = (long long)floor((double)tt * ratio);
        }
        if (slot > (long long)(total - 1)) slot = total - 1;
        if (slot < 0) slot = 0;

        int lo = 0, hi = K;
        const int si = (int)slot;
        while (hi - lo > 1) {
            int mid = (lo + hi) >> 1;
            if (s_cum[mid] <= si) lo = mid; else hi = mid;
        }
        const int k = lo;
        const int j = si - s_cum[k];

        const float Lp = s_Lp[k];
        const float x  = __fadd_rn(__fdiv_rn(__fadd_rn(__fmul_rn(2.0f, (float)j), 1.0f), lmaxf), -1.0f);
        const float s  = __fdiv_rn(lmaxf, Lp);
        const float tl = __fdiv_rn(__fadd_rn(lmaxf, -Lp), Lp);
        const float xs = __fadd_rn(__fmul_rn(s, x), tl);
        const float p  = __fmul_rn(__fadd_rn(__fmul_rn(__fadd_rn(xs, 1.0f), 100.0f), -1.0f), 0.5f);
        const float p0 = floorf(p);
        const float w1 = __fadd_rn(p, -p0);
        const float in0 = (p0 >=  0.0f && p0 <= 99.0f) ? 1.0f : 0.0f;
        const float in1 = (p0 >= -1.0f && p0 <= 98.0f) ? 1.0f : 0.0f;
        wv[i] = __fadd_rn(__fmul_rn(__fadd_rn(1.0f, -w1), in0), __fmul_rn(w1, in1));
        kv[i] = k;
    }

    if (tt0 + 3 < T) {
        *reinterpret_cast<float4*>(&d_w[tt0]) = make_float4(wv[0], wv[1], wv[2], wv[3]);
        *reinterpret_cast<int4*>  (&d_k[tt0]) = make_int4(kv[0], kv[1], kv[2], kv[3]);
    } else {
        for (int i = 0; i < 4 && tt0 + i < T; i++) {
            d_w[tt0 + i] = wv[i];
            d_k[tt0 + i] = kv[i];
        }
    }
}

// ---------------------------------------------------------------------------
// Fill kernel (hot). 256 threads, 4 cols/thread, CPB rows/block.
// Prefetch all CPB A-values (MLP=CPB), then stream independent stores.
// ---------------------------------------------------------------------------
__global__ void __launch_bounds__(256) fill_kernel(
    const float* __restrict__ A,
    float* __restrict__ out,
    int K, int T, int C)
{
    const int tt0 = (blockIdx.x * blockDim.x + threadIdx.x) * 4;
    if (tt0 >= T) return;

    const bool vec = (tt0 + 3 < T);

    float4 w;
    int4   k;
    if (vec) {
        w = *reinterpret_cast<const float4*>(&d_w[tt0]);
        k = *reinterpret_cast<const int4*>  (&d_k[tt0]);
    } else {
        w = make_float4(d_w[tt0], 0.f, 0.f, 0.f);
        k = make_int4(d_k[tt0], 0, 0, 0);
        if (tt0 + 1 < T) { w.y = d_w[tt0 + 1]; k.y = d_k[tt0 + 1]; }
        if (tt0 + 2 < T) { w.z = d_w[tt0 + 2]; k.z = d_k[tt0 + 2]; }
    }

    const int c0 = blockIdx.y * CPB;
    const bool fullc = (c0 + CPB <= C);

    // k monotone non-decreasing: ends equal => all four equal.
    if ((k.x == k.w) & vec & fullc) {
        const float* Ap = A + (size_t)c0 * (size_t)K + k.x;
        float a[CPB];
#pragma unroll
        for (int i = 0; i < CPB; i++) a[i] = __ldg(Ap + (size_t)i * K);

        float* op = out + (size_t)c0 * (size_t)T + tt0;
#pragma unroll
        for (int i = 0; i < CPB; i++) {
            __stcs(reinterpret_cast<float4*>(op),
                   make_float4(a[i] * w.x, a[i] * w.y, a[i] * w.z, a[i] * w.w));
            op += T;
        }
    } else {
        int c1 = c0 + CPB; if (c1 > C) c1 = C;
        for (int c = c0; c < c1; ++c) {
            const float* Ar = A + (size_t)c * (size_t)K;
            float4 o;
            o.x = __ldg(Ar + k.x) * w.x;
            o.y = __ldg(Ar + k.y) * w.y;
            o.z = __ldg(Ar + k.z) * w.z;
            o.w = __ldg(Ar + k.w) * w.w;
            float* op = out + (size_t)c * (size_t)T + tt0;
            if (vec) {
                __stcs(reinterpret_cast<float4*>(op), o);
            } else {
                if (tt0     < T) op[0] = o.x;
                if (tt0 + 1 < T) op[1] = o.y;
                if (tt0 + 2 < T) op[2] = o.z;
                if (tt0 + 3 < T) op[3] = o.w;
            }
        }
    }
}

// ---------------------------------------------------------------------------
extern "C" void kernel_launch(void* const* d_in, const int* in_sizes, int n_in,
                              void* d_out, int out_size)
{
    const float* A = (const float*)d_in[0];   // [C, K]
    const float* L = (const float*)d_in[1];   // [K]

    const int K = in_sizes[1];
    const int C = in_sizes[0] / K;
    const int T = out_size / C;               // out is [1, C, T]

    plan_kernel<<<1, 32>>>(L, K, (float)T);

    const int cols_per_block = 256 * 4;
    const int gx = (T + cols_per_block - 1) / cols_per_block;

    expand_kernel<<<gx, 256>>>(K, T);

    dim3 grid(gx, (C + CPB - 1) / CPB);
    fill_kernel<<<grid, 256>>>(A, (float*)d_out, K, T, C);
}

// round 5
// speedup vs baseline: 1.0684x; 1.0684x over previous
#include <cuda_runtime.h>
#include <math.h>
#include <stdint.h>

// ============================================================================
// TemporalSamplingUpSampler — 3-phase:
//   1) plan_kernel  <<<1,256>>> : block-parallel plan, one k per thread,
//                                 register-resident, ~8 barriers.
//   2) expand_kernel<<<128,256>>>: plan -> smem, per-column (k, w) via
//                                 LDS binary search. Writes d_w[T], d_k[T].
//   3) fill_kernel  (hot)       : out[c,tt] = A[c,k[tt]] * w[tt].
//                                 float4 evict-first stores. HBM-write bound.
// ============================================================================

#define MAX_K 1024
#define MAX_T (1 << 18)

__device__ float d_Lp[MAX_K];
__device__ int   d_cum[MAX_K + 1];
__device__ int   d_total;
__device__ float d_lmaxf;

__device__ float d_w[MAX_T];
__device__ int   d_k[MAX_T];

// ---------------------------------------------------------------------------
// Plan kernel: one 256-thread block, EPT<=4 elements/thread, all in registers.
// ---------------------------------------------------------------------------
__global__ void __launch_bounds__(256) plan_kernel(
    const float* __restrict__ L, int K, float Tf)
{
    __shared__ float sred[32];
    __shared__ int   sscan[32];

    const int t    = threadIdx.x;
    const int lane = t & 31;
    const int warp = t >> 5;
    const int nw   = blockDim.x >> 5;              // 8
    const int EPT  = (K + blockDim.x - 1) / blockDim.x;   // 1 for K=256
    const int base = t * EPT;

    float lv[4];
#pragma unroll
    for (int i = 0; i < 4; i++) {
        int k = base + i;
        lv[i] = (i < EPT && k < K) ? __ldg(L + k) : -INFINITY;
    }

    // ---- block max(L) ----
    float mx = fmaxf(fmaxf(lv[0], lv[1]), fmaxf(lv[2], lv[3]));
    for (int o = 16; o; o >>= 1) mx = fmaxf(mx, __shfl_xor_sync(0xffffffffu, mx, o));
    if (lane == 0) sred[warp] = mx;
    __syncthreads();
    if (warp == 0) {
        float v = (lane < nw) ? sred[lane] : -INFINITY;
        for (int o = 16; o; o >>= 1) v = fmaxf(v, __shfl_xor_sync(0xffffffffu, v, o));
        if (lane == 0) sred[0] = v;
    }
    __syncthreads();
    mx = sred[0];
    __syncthreads();

    // ---- block sum(exp) ----
    float e[4];
    float s = 0.0f;
#pragma unroll
    for (int i = 0; i < 4; i++) {
        int k = base + i;
        e[i] = (i < EPT && k < K) ? expf(lv[i] - mx) : 0.0f;
        s += e[i];
    }
    for (int o = 16; o; o >>= 1) s += __shfl_xor_sync(0xffffffffu, s, o);
    if (lane == 0) sred[warp] = s;
    __syncthreads();
    if (warp == 0) {
        float v = (lane < nw) ? sred[lane] : 0.0f;
        for (int o = 16; o; o >>= 1) v += __shfl_xor_sync(0xffffffffu, v, o);
        if (lane == 0) sred[0] = v;
    }
    __syncthreads();
    const float sum = sred[0];
    __syncthreads();

    // ---- Lp, r = max(rint(Lp),0), maxLp ----
    float maxLp = -INFINITY;
    int rr[4];
    int rs = 0;
#pragma unroll
    for (int i = 0; i < 4; i++) {
        int k = base + i;
        if (i < EPT && k < K) {
            float Lp = Tf * __fdiv_rn(e[i], sum);
            d_Lp[k] = Lp;
            maxLp = fmaxf(maxLp, Lp);
            int r = (int)rintf(Lp);        // half-to-even == np.rint
            if (r < 0) r = 0;
            rr[i] = r;
            rs += r;
        } else rr[i] = 0;
    }

    // ---- block max(Lp) ----
    float mLp = maxLp;
    for (int o = 16; o; o >>= 1) mLp = fmaxf(mLp, __shfl_xor_sync(0xffffffffu, mLp, o));
    if (lane == 0) sred[warp] = mLp;
    __syncthreads();
    if (warp == 0) {
        float v = (lane < nw) ? sred[lane] : -INFINITY;
        for (int o = 16; o; o >>= 1) v = fmaxf(v, __shfl_xor_sync(0xffffffffu, v, o));
        if (lane == 0) sred[0] = v;
    }

    // ---- block scan of rs (two-level shfl) ----
    int incl = rs;
    for (int o = 1; o < 32; o <<= 1) {
        int v = __shfl_up_sync(0xffffffffu, incl, o);
        if (lane >= o) incl += v;
    }
    if (lane == 31) sscan[warp] = incl;
    __syncthreads();
    if (warp == 0) {
        int v = (lane < nw) ? sscan[lane] : 0;
        for (int o = 1; o < 32; o <<= 1) {
            int u = __shfl_up_sync(0xffffffffu, v, o);
            if (lane >= o) v += u;
        }
        if (lane < nw) sscan[lane] = v;    // inclusive warp totals
    }
    __syncthreads();

    const int warp_excl = (warp == 0) ? 0 : sscan[warp - 1];
    int running = warp_excl + (incl - rs);     // exclusive prefix for this thread
#pragma unroll
    for (int i = 0; i < 4; i++) {
        int k = base + i;
        if (i < EPT && k < K) {
            running += rr[i];
            d_cum[k + 1] = running;
        }
    }

    if (t == 0) {
        d_cum[0] = 0;
        d_total  = sscan[nw - 1];
        double dm = (double)sred[0] + 0.5;
        d_lmaxf = (float)(long long)dm;    // int(max+0.5), trunc==floor (>=0)
    }
}

// ---------------------------------------------------------------------------
// Expand kernel: plan -> smem, then 4 columns/thread.
// ---------------------------------------------------------------------------
__global__ void __launch_bounds__(256) expand_kernel(int K, int T)
{
    __shared__ float s_Lp[MAX_K];
    __shared__ int   s_cum[MAX_K + 1];

    for (int k = threadIdx.x; k < K; k += blockDim.x) {
        s_Lp[k]      = d_Lp[k];
        s_cum[k + 1] = d_cum[k + 1];
    }
    if (threadIdx.x == 0) s_cum[0] = 0;
    __syncthreads();

    const int tt0 = (blockIdx.x * blockDim.x + threadIdx.x) * 4;
    if (tt0 >= T) return;

    const int   total = d_total;
    const float lmaxf = d_lmaxf;

    const bool  pow2  = (T & (T - 1)) == 0;
    const int   shift = __ffs(T) - 1;
    const double ratio = (double)total / (double)T;

    float wv[4];
    int   kv[4];

#pragma unroll
    for (int i = 0; i < 4; i++) {
        int tt = tt0 + i;
        if (tt > T - 1) tt = T - 1;

        long long slot;
        if (pow2) {
            slot = ((long long)tt * (long long)total) >> shift;  // exact
        } else {
            slot = (long long)floor((double)tt * ratio);
        }
        if (slot > (long long)(total - 1)) slot = total - 1;
        if (slot < 0) slot = 0;

        int lo = 0, hi = K;
        const int si = (int)slot;
        while (hi - lo > 1) {
            int mid = (lo + hi) >> 1;
            if (s_cum[mid] <= si) lo = mid; else hi = mid;
        }
        const int k = lo;
        const int j = si - s_cum[k];

        const float Lp = s_Lp[k];
        const float x  = __fadd_rn(__fdiv_rn(__fadd_rn(__fmul_rn(2.0f, (float)j), 1.0f), lmaxf), -1.0f);
        const float s  = __fdiv_rn(lmaxf, Lp);
        const float tl = __fdiv_rn(__fadd_rn(lmaxf, -Lp), Lp);
        const float xs = __fadd_rn(__fmul_rn(s, x), tl);
        const float p  = __fmul_rn(__fadd_rn(__fmul_rn(__fadd_rn(xs, 1.0f), 100.0f), -1.0f), 0.5f);
        const float p0 = floorf(p);
        const float w1 = __fadd_rn(p, -p0);
        const float in0 = (p0 >=  0.0f && p0 <= 99.0f) ? 1.0f : 0.0f;
        const float in1 = (p0 >= -1.0f && p0 <= 98.0f) ? 1.0f : 0.0f;
        wv[i] = __fadd_rn(__fmul_rn(__fadd_rn(1.0f, -w1), in0), __fmul_rn(w1, in1));
        kv[i] = k;
    }

    if (tt0 + 3 < T) {
        *reinterpret_cast<float4*>(&d_w[tt0]) = make_float4(wv[0], wv[1], wv[2], wv[3]);
        *reinterpret_cast<int4*>  (&d_k[tt0]) = make_int4(kv[0], kv[1], kv[2], kv[3]);
    } else {
        for (int i = 0; i < 4 && tt0 + i < T; i++) {
            d_w[tt0 + i] = wv[i];
            d_k[tt0 + i] = kv[i];
        }
    }
}

// ---------------------------------------------------------------------------
// Fill kernel (hot) — round-3 known-good version.
// ---------------------------------------------------------------------------
__global__ void __launch_bounds__(256) fill_kernel(
    const float* __restrict__ A,
    float* __restrict__ out,
    int K, int T, int C, int c_per_block)
{
    const int tt0 = (blockIdx.x * blockDim.x + threadIdx.x) * 4;
    if (tt0 >= T) return;

    const bool vec = (tt0 + 3 < T);

    float4 w;
    int4   k;
    if (vec) {
        w = *reinterpret_cast<const float4*>(&d_w[tt0]);
        k = *reinterpret_cast<const int4*>  (&d_k[tt0]);
    } else {
        w = make_float4(d_w[tt0], 0.f, 0.f, 0.f);
        k = make_int4(d_k[tt0], 0, 0, 0);
        if (tt0 + 1 < T) { w.y = d_w[tt0 + 1]; k.y = d_k[tt0 + 1]; }
        if (tt0 + 2 < T) { w.z = d_w[tt0 + 2]; k.z = d_k[tt0 + 2]; }
    }

    const int c0 = blockIdx.y * c_per_block;
    int c1 = c0 + c_per_block;
    if (c1 > C) c1 = C;

    // k monotone non-decreasing: ends equal => all four equal.
    const bool same = (k.x == k.w);

    if (same & vec) {
        const float* Ap = A + (size_t)c0 * (size_t)K + k.x;
        float* op = out + (size_t)c0 * (size_t)T + tt0;
#pragma unroll 4
        for (int c = c0; c < c1; ++c) {
            const float a = __ldg(Ap);
            float4 o = make_float4(a * w.x, a * w.y, a * w.z, a * w.w);
            __stcs(reinterpret_cast<float4*>(op), o);
            Ap += K;
            op += T;
        }
    } else {
        for (int c = c0; c < c1; ++c) {
            const float* Ar = A + (size_t)c * (size_t)K;
            float4 o;
            o.x = __ldg(Ar + k.x) * w.x;
            o.y = __ldg(Ar + k.y) * w.y;
            o.z = __ldg(Ar + k.z) * w.z;
            o.w = __ldg(Ar + k.w) * w.w;
            float* op = out + (size_t)c * (size_t)T + tt0;
            if (vec) {
                __stcs(reinterpret_cast<float4*>(op), o);
            } else {
                if (tt0     < T) op[0] = o.x;
                if (tt0 + 1 < T) op[1] = o.y;
                if (tt0 + 2 < T) op[2] = o.z;
                if (tt0 + 3 < T) op[3] = o.w;
            }
        }
    }
}

// ---------------------------------------------------------------------------
extern "C" void kernel_launch(void* const* d_in, const int* in_sizes, int n_in,
                              void* d_out, int out_size)
{
    const float* A = (const float*)d_in[0];   // [C, K]
    const float* L = (const float*)d_in[1];   // [K]

    const int K = in_sizes[1];
    const int C = in_sizes[0] / K;
    const int T = out_size / C;               // out is [1, C, T]

    plan_kernel<<<1, 256>>>(L, K, (float)T);

    const int cols_per_block = 256 * 4;
    const int gx = (T + cols_per_block - 1) / cols_per_block;

    expand_kernel<<<gx, 256>>>(K, T);

    const int c_per_block = 8;
    dim3 grid(gx, (C + c_per_block - 1) / c_per_block);
    fill_kernel<<<grid, 256>>>(A, (float*)d_out, K, T, C, c_per_block);
}

// round 6
// speedup vs baseline: 1.1385x; 1.0656x over previous
#include <cuda_runtime.h>
#include <math.h>
#include <stdint.h>

// ============================================================================
// TemporalSamplingUpSampler — 2-phase:
//   1) expand_kernel<<<T/1024,256>>>: EVERY block computes the plan
//      block-parallel (1 k per thread, shfl+smem reductions, ~8 barriers)
//      directly into smem, then expands its 1024 output columns:
//      slot -> (k, w). Writes d_w[T], d_k[T]. No separate plan kernel,
//      no global plan arrays — kills the ~5-6us tiny-kernel floor.
//   2) fill_kernel (hot, round-3 known-good): out[c,tt] = A[c,k[tt]]*w[tt],
//      broadcast A reads, float4 evict-first stores. HBM-write bound.
// ============================================================================

#define MAX_K 1024
#define MAX_T (1 << 18)

__device__ float d_w[MAX_T];
__device__ int   d_k[MAX_T];

// ---------------------------------------------------------------------------
// Expand kernel with fused block-parallel plan.
// ---------------------------------------------------------------------------
__global__ void __launch_bounds__(256) expand_kernel(
    const float* __restrict__ L, int K, int T, float Tf)
{
    __shared__ float s_Lp[MAX_K];
    __shared__ int   s_cum[MAX_K + 1];
    __shared__ float sred[32];
    __shared__ int   sscan[32];
    __shared__ int   s_total;
    __shared__ float s_lmax;

    const int t    = threadIdx.x;
    const int lane = t & 31;
    const int warp = t >> 5;
    const int nw   = blockDim.x >> 5;                     // 8
    const int EPT  = (K + blockDim.x - 1) / blockDim.x;   // 1 for K=256
    const int base = t * EPT;

    // ---------------- plan (all 256 threads) ----------------
    float lv[4];
#pragma unroll
    for (int i = 0; i < 4; i++) {
        int k = base + i;
        lv[i] = (i < EPT && k < K) ? __ldg(L + k) : -INFINITY;
    }

    // block max(L)
    float mx = fmaxf(fmaxf(lv[0], lv[1]), fmaxf(lv[2], lv[3]));
    for (int o = 16; o; o >>= 1) mx = fmaxf(mx, __shfl_xor_sync(0xffffffffu, mx, o));
    if (lane == 0) sred[warp] = mx;
    __syncthreads();
    if (warp == 0) {
        float v = (lane < nw) ? sred[lane] : -INFINITY;
        for (int o = 16; o; o >>= 1) v = fmaxf(v, __shfl_xor_sync(0xffffffffu, v, o));
        if (lane == 0) sred[0] = v;
    }
    __syncthreads();
    mx = sred[0];
    __syncthreads();

    // block sum(exp)
    float e[4];
    float s = 0.0f;
#pragma unroll
    for (int i = 0; i < 4; i++) {
        int k = base + i;
        e[i] = (i < EPT && k < K) ? expf(lv[i] - mx) : 0.0f;
        s += e[i];
    }
    for (int o = 16; o; o >>= 1) s += __shfl_xor_sync(0xffffffffu, s, o);
    if (lane == 0) sred[warp] = s;
    __syncthreads();
    if (warp == 0) {
        float v = (lane < nw) ? sred[lane] : 0.0f;
        for (int o = 16; o; o >>= 1) v += __shfl_xor_sync(0xffffffffu, v, o);
        if (lane == 0) sred[0] = v;
    }
    __syncthreads();
    const float sum = sred[0];
    __syncthreads();

    // Lp -> smem, r = max(rint(Lp),0), maxLp
    float maxLp = -INFINITY;
    int rr[4];
    int rs = 0;
#pragma unroll
    for (int i = 0; i < 4; i++) {
        int k = base + i;
        if (i < EPT && k < K) {
            float Lp = Tf * __fdiv_rn(e[i], sum);
            s_Lp[k] = Lp;
            maxLp = fmaxf(maxLp, Lp);
            int r = (int)rintf(Lp);        // half-to-even == np.rint
            if (r < 0) r = 0;
            rr[i] = r;
            rs += r;
        } else rr[i] = 0;
    }

    // block max(Lp)
    float mLp = maxLp;
    for (int o = 16; o; o >>= 1) mLp = fmaxf(mLp, __shfl_xor_sync(0xffffffffu, mLp, o));
    if (lane == 0) sred[warp] = mLp;
    __syncthreads();
    if (warp == 0) {
        float v = (lane < nw) ? sred[lane] : -INFINITY;
        for (int o = 16; o; o >>= 1) v = fmaxf(v, __shfl_xor_sync(0xffffffffu, v, o));
        if (lane == 0) sred[0] = v;
    }

    // block scan of rs (two-level shfl)
    int incl = rs;
    for (int o = 1; o < 32; o <<= 1) {
        int v = __shfl_up_sync(0xffffffffu, incl, o);
        if (lane >= o) incl += v;
    }
    if (lane == 31) sscan[warp] = incl;
    __syncthreads();
    if (warp == 0) {
        int v = (lane < nw) ? sscan[lane] : 0;
        for (int o = 1; o < 32; o <<= 1) {
            int u = __shfl_up_sync(0xffffffffu, v, o);
            if (lane >= o) v += u;
        }
        if (lane < nw) sscan[lane] = v;    // inclusive warp totals
    }
    __syncthreads();

    const int warp_excl = (warp == 0) ? 0 : sscan[warp - 1];
    int running = warp_excl + (incl - rs);     // exclusive prefix, this thread
#pragma unroll
    for (int i = 0; i < 4; i++) {
        int k = base + i;
        if (i < EPT && k < K) {
            running += rr[i];
            s_cum[k + 1] = running;
        }
    }
    if (t == 0) {
        s_cum[0] = 0;
        s_total  = sscan[nw - 1];
        double dm = (double)sred[0] + 0.5;
        s_lmax = (float)(long long)dm;     // int(max+0.5), trunc==floor (>=0)
    }
    __syncthreads();

    // ---------------- expansion (4 columns / thread) ----------------
    const int tt0 = (blockIdx.x * blockDim.x + threadIdx.x) * 4;
    if (tt0 >= T) return;

    const int   total = s_total;
    const float lmaxf = s_lmax;

    const bool  pow2  = (T & (T - 1)) == 0;
    const int   shift = __ffs(T) - 1;
    const double ratio = (double)total / (double)T;

    float wv[4];
    int   kv[4];

#pragma unroll
    for (int i = 0; i < 4; i++) {
        int tt = tt0 + i;
        if (tt > T - 1) tt = T - 1;

        long long slot;
        if (pow2) {
            slot = ((long long)tt * (long long)total) >> shift;  // exact
        } else {
            slot = (long long)floor((double)tt * ratio);
        }
        if (slot > (long long)(total - 1)) slot = total - 1;
        if (slot < 0) slot = 0;

        int lo = 0, hi = K;
        const int si = (int)slot;
        while (hi - lo > 1) {
            int mid = (lo + hi) >> 1;
            if (s_cum[mid] <= si) lo = mid; else hi = mid;
        }
        const int k = lo;
        const int j = si - s_cum[k];

        const float Lp = s_Lp[k];
        const float x  = __fadd_rn(__fdiv_rn(__fadd_rn(__fmul_rn(2.0f, (float)j), 1.0f), lmaxf), -1.0f);
        const float sc = __fdiv_rn(lmaxf, Lp);
        const float tl = __fdiv_rn(__fadd_rn(lmaxf, -Lp), Lp);
        const float xs = __fadd_rn(__fmul_rn(sc, x), tl);
        const float p  = __fmul_rn(__fadd_rn(__fmul_rn(__fadd_rn(xs, 1.0f), 100.0f), -1.0f), 0.5f);
        const float p0 = floorf(p);
        const float w1 = __fadd_rn(p, -p0);
        const float in0 = (p0 >=  0.0f && p0 <= 99.0f) ? 1.0f : 0.0f;
        const float in1 = (p0 >= -1.0f && p0 <= 98.0f) ? 1.0f : 0.0f;
        wv[i] = __fadd_rn(__fmul_rn(__fadd_rn(1.0f, -w1), in0), __fmul_rn(w1, in1));
        kv[i] = k;
    }

    if (tt0 + 3 < T) {
        *reinterpret_cast<float4*>(&d_w[tt0]) = make_float4(wv[0], wv[1], wv[2], wv[3]);
        *reinterpret_cast<int4*>  (&d_k[tt0]) = make_int4(kv[0], kv[1], kv[2], kv[3]);
    } else {
        for (int i = 0; i < 4 && tt0 + i < T; i++) {
            d_w[tt0 + i] = wv[i];
            d_k[tt0 + i] = kv[i];
        }
    }
}

// ---------------------------------------------------------------------------
// Fill kernel (hot) — round-3 known-good version, unchanged.
// ---------------------------------------------------------------------------
__global__ void __launch_bounds__(256) fill_kernel(
    const float* __restrict__ A,
    float* __restrict__ out,
    int K, int T, int C, int c_per_block)
{
    const int tt0 = (blockIdx.x * blockDim.x + threadIdx.x) * 4;
    if (tt0 >= T) return;

    const bool vec = (tt0 + 3 < T);

    float4 w;
    int4   k;
    if (vec) {
        w = *reinterpret_cast<const float4*>(&d_w[tt0]);
        k = *reinterpret_cast<const int4*>  (&d_k[tt0]);
    } else {
        w = make_float4(d_w[tt0], 0.f, 0.f, 0.f);
        k = make_int4(d_k[tt0], 0, 0, 0);
        if (tt0 + 1 < T) { w.y = d_w[tt0 + 1]; k.y = d_k[tt0 + 1]; }
        if (tt0 + 2 < T) { w.z = d_w[tt0 + 2]; k.z = d_k[tt0 + 2]; }
    }

    const int c0 = blockIdx.y * c_per_block;
    int c1 = c0 + c_per_block;
    if (c1 > C) c1 = C;

    // k monotone non-decreasing: ends equal => all four equal.
    const bool same = (k.x == k.w);

    if (same & vec) {
        const float* Ap = A + (size_t)c0 * (size_t)K + k.x;
        float* op = out + (size_t)c0 * (size_t)T + tt0;
#pragma unroll 4
        for (int c = c0; c < c1; ++c) {
            const float a = __ldg(Ap);
            float4 o = make_float4(a * w.x, a * w.y, a * w.z, a * w.w);
            __stcs(reinterpret_cast<float4*>(op), o);
            Ap += K;
            op += T;
        }
    } else {
        for (int c = c0; c < c1; ++c) {
            const float* Ar = A + (size_t)c * (size_t)K;
            float4 o;
            o.x = __ldg(Ar + k.x) * w.x;
            o.y = __ldg(Ar + k.y) * w.y;
            o.z = __ldg(Ar + k.z) * w.z;
            o.w = __ldg(Ar + k.w) * w.w;
            float* op = out + (size_t)c * (size_t)T + tt0;
            if (vec) {
                __stcs(reinterpret_cast<float4*>(op), o);
            } else {
                if (tt0     < T) op[0] = o.x;
                if (tt0 + 1 < T) op[1] = o.y;
                if (tt0 + 2 < T) op[2] = o.z;
                if (tt0 + 3 < T) op[3] = o.w;
            }
        }
    }
}

// ---------------------------------------------------------------------------
extern "C" void kernel_launch(void* const* d_in, const int* in_sizes, int n_in,
                              void* d_out, int out_size)
{
    const float* A = (const float*)d_in[0];   // [C, K]
    const float* L = (const float*)d_in[1];   // [K]

    const int K = in_sizes[1];
    const int C = in_sizes[0] / K;
    const int T = out_size / C;               // out is [1, C, T]

    const int cols_per_block = 256 * 4;
    const int gx = (T + cols_per_block - 1) / cols_per_block;

    expand_kernel<<<gx, 256>>>(L, K, T, (float)T);

    const int c_per_block = 8;
    dim3 grid(gx, (C + c_per_block - 1) / c_per_block);
    fill_kernel<<<grid, 256>>>(A, (float*)d_out, K, T, C, c_per_block);
}